// round 1
// baseline (speedup 1.0000x reference)
#include <cuda_runtime.h>

// Problem constants
#define B_ 16
#define K_ 49
#define T_ 256
#define H_ 512
#define D_ 512

// Output packing: (c_hat_t, alpha_t, beta_t) flattened in order
#define OUT_ALPHA (B_ * T_ * H_)              // 2097152
#define OUT_BETA  (OUT_ALPHA + B_ * T_ * K_)  // 2297856

// Scratch (device globals: allocation-free)
__device__ float g_cv[B_ * K_ * D_];   // V @ Wv + bv
__device__ float g_cg[B_ * T_ * D_];   // h_t @ Wg + bg
__device__ float g_cs[B_ * T_ * D_];   // s_t @ Ws + bs   (cg added later, in-register)

// ---------------------------------------------------------------------------
// GEMM: C[M,512] = A[M,512] @ W[512,512] + bias, fp32 SIMT, 128x128x8 tiles
// which: 0 -> g_cv, 1 -> g_cg, 2 -> g_cs
// ---------------------------------------------------------------------------
__global__ __launch_bounds__(256)
void gemm_bias_kernel(const float* __restrict__ A, const float* __restrict__ W,
                      const float* __restrict__ bias, int which, int M)
{
    float* __restrict__ C = (which == 0) ? g_cv : (which == 1) ? g_cg : g_cs;

    __shared__ float As[8][132];   // padded to kill store conflicts
    __shared__ float Bs[8][128];

    const int tid = threadIdx.x;
    const int bx = blockIdx.x, by = blockIdx.y;
    const int tx = tid & 15, ty = tid >> 4;

    float acc[8][8];
    #pragma unroll
    for (int i = 0; i < 8; i++)
        #pragma unroll
        for (int j = 0; j < 8; j++) acc[i][j] = 0.f;

    const int arow  = by * 128 + (tid >> 1);
    const int acol4 = (tid & 1) * 4;
    const int wrow  = tid >> 5;
    const int wcol4 = bx * 128 + (tid & 31) * 4;

    for (int kt = 0; kt < 512; kt += 8) {
        float4 av = make_float4(0.f, 0.f, 0.f, 0.f);
        if (arow < M)
            av = *reinterpret_cast<const float4*>(&A[arow * 512 + kt + acol4]);
        As[acol4 + 0][tid >> 1] = av.x;
        As[acol4 + 1][tid >> 1] = av.y;
        As[acol4 + 2][tid >> 1] = av.z;
        As[acol4 + 3][tid >> 1] = av.w;

        float4 wv = *reinterpret_cast<const float4*>(&W[(kt + wrow) * 512 + wcol4]);
        *reinterpret_cast<float4*>(&Bs[wrow][(tid & 31) * 4]) = wv;

        __syncthreads();
        #pragma unroll
        for (int kk = 0; kk < 8; kk++) {
            float a[8], b[8];
            #pragma unroll
            for (int j = 0; j < 8; j++) a[j] = As[kk][ty * 8 + j];
            #pragma unroll
            for (int j = 0; j < 8; j++) b[j] = Bs[kk][tx * 8 + j];
            #pragma unroll
            for (int i = 0; i < 8; i++)
                #pragma unroll
                for (int j = 0; j < 8; j++)
                    acc[i][j] = fmaf(a[i], b[j], acc[i][j]);
        }
        __syncthreads();
    }

    #pragma unroll
    for (int i = 0; i < 8; i++) {
        const int row = by * 128 + ty * 8 + i;
        if (row >= M) continue;
        #pragma unroll
        for (int j = 0; j < 8; j++) {
            const int col = bx * 128 + tx * 8 + j;
            C[row * 512 + col] = acc[i][j] + bias[col];
        }
    }
}

// tanh(x) = 1 - 2/(exp(2x)+1), computed from m = 2x*log2(e).
// ex2.approx + rcp.approx: ~1e-7 abs error, 2 MUFU ops.
__device__ __forceinline__ float tanh_from_m(float m)
{
    float e, r;
    asm("ex2.approx.f32 %0, %1;" : "=f"(e) : "f"(m));
    asm("rcp.approx.f32 %0, %1;" : "=f"(r) : "f"(e + 1.0f));
    return fmaf(-2.0f, r, 1.0f);
}

#define TWO_LOG2E 2.8853900817779268f

// ---------------------------------------------------------------------------
// Fused: z_t (tanh-dot), z_ext, softmaxes, c_t = alpha@V, blend, outputs.
// Grid: B*(T/8) = 512 blocks, 256 threads (8 warps). Warp w handles t = tile*8+w.
// ---------------------------------------------------------------------------
__global__ __launch_bounds__(256)
void fused_attn_kernel(const float* __restrict__ V, const float* __restrict__ s_t,
                       const float* __restrict__ Wh, const float* __restrict__ bh,
                       float* __restrict__ out)
{
    __shared__ float whs[512];
    __shared__ float buf[2][512];
    __shared__ float z_s[8][64];
    __shared__ float alpha_s[8][52];
    __shared__ float beta_s[8];

    const int tid  = threadIdx.x;
    const int lane = tid & 31;
    const int w    = tid >> 5;
    const int b     = blockIdx.x >> 5;
    const int ttile = blockIdx.x & 31;
    const int t  = ttile * 8 + w;
    const int bt = b * T_ + t;

    // Wh into smem
    whs[tid]       = Wh[tid];
    whs[tid + 256] = Wh[tid + 256];

    // cg row for this t, pre-scaled by 2*log2(e), register-resident
    const float* __restrict__ cgrow = g_cg + (size_t)bt * 512;
    float cg2[16];
    #pragma unroll
    for (int i = 0; i < 16; i++) cg2[i] = cgrow[i * 32 + lane] * TWO_LOG2E;

    const float bhv = bh[0];

    // ---- z_t over k, with smem-shared cv rows (double-buffered) ----
    const float* __restrict__ cvb = g_cv + (size_t)b * (K_ * 512);
    float2 pre = *reinterpret_cast<const float2*>(&cvb[tid * 2]);

    for (int k = 0; k < K_; k++) {
        *reinterpret_cast<float2*>(&buf[k & 1][tid * 2]) = pre;
        __syncthreads();
        if (k < K_ - 1)
            pre = *reinterpret_cast<const float2*>(&cvb[(k + 1) * 512 + tid * 2]);

        const float* __restrict__ bb = buf[k & 1];
        float acc = 0.f;
        #pragma unroll
        for (int i = 0; i < 16; i++) {
            float m  = fmaf(bb[i * 32 + lane], TWO_LOG2E, cg2[i]);
            float th = tanh_from_m(m);
            acc = fmaf(th, whs[i * 32 + lane], acc);
        }
        #pragma unroll
        for (int o = 16; o > 0; o >>= 1)
            acc += __shfl_xor_sync(0xffffffffu, acc, o);
        if (lane == 0) z_s[w][k] = acc + bhv;
    }

    // ---- z_ext from content_s = cs_raw + cg (per-warp, no block sync) ----
    {
        const float* __restrict__ csrow = g_cs + (size_t)bt * 512;
        float acc = 0.f;
        #pragma unroll
        for (int i = 0; i < 16; i++) {
            float m  = fmaf(csrow[i * 32 + lane], TWO_LOG2E, cg2[i]);
            float th = tanh_from_m(m);
            acc = fmaf(th, whs[i * 32 + lane], acc);
        }
        #pragma unroll
        for (int o = 16; o > 0; o >>= 1)
            acc += __shfl_xor_sync(0xffffffffu, acc, o);
        if (lane == 0) z_s[w][K_] = acc + bhv;
    }
    __syncwarp();

    // ---- softmaxes: alpha over 49, beta from extended 50 ----
    {
        float z0 = (lane < K_)      ? z_s[w][lane]      : -1e30f;
        float z1 = (lane + 32 < K_) ? z_s[w][lane + 32] : -1e30f;
        float ze = z_s[w][K_];
        float m = fmaxf(fmaxf(z0, z1), ze);
        #pragma unroll
        for (int o = 16; o > 0; o >>= 1)
            m = fmaxf(m, __shfl_xor_sync(0xffffffffu, m, o));

        float e0 = (lane < K_)      ? __expf(z0 - m) : 0.f;
        float e1 = (lane + 32 < K_) ? __expf(z1 - m) : 0.f;
        float ee = __expf(ze - m);

        float s = e0 + e1;
        #pragma unroll
        for (int o = 16; o > 0; o >>= 1)
            s += __shfl_xor_sync(0xffffffffu, s, o);
        const float s49 = s;
        const float beta = ee / (s49 + ee);
        const float inv49 = 1.0f / s49;

        if (lane < K_) {
            float a0 = e0 * inv49;
            alpha_s[w][lane] = a0;
            out[OUT_ALPHA + (size_t)bt * K_ + lane] = a0;
        }
        if (lane + 32 < K_) {
            float a1 = e1 * inv49;
            alpha_s[w][lane + 32] = a1;
            out[OUT_ALPHA + (size_t)bt * K_ + lane + 32] = a1;
        }
        if (lane == 0) {
            beta_s[w] = beta;
            out[OUT_BETA + bt] = beta;
        }
    }

    // ---- c_t = alpha @ V, with smem-shared V rows ----
    float cacc[16];
    #pragma unroll
    for (int i = 0; i < 16; i++) cacc[i] = 0.f;

    const float* __restrict__ Vb = V + (size_t)b * (K_ * 512);
    pre = *reinterpret_cast<const float2*>(&Vb[tid * 2]);
    __syncthreads();   // everyone done reading buf from the z-loop

    for (int k = 0; k < K_; k++) {
        *reinterpret_cast<float2*>(&buf[k & 1][tid * 2]) = pre;
        __syncthreads();
        if (k < K_ - 1)
            pre = *reinterpret_cast<const float2*>(&Vb[(k + 1) * 512 + tid * 2]);

        const float a = alpha_s[w][k];
        const float* __restrict__ bb = buf[k & 1];
        #pragma unroll
        for (int i = 0; i < 16; i++)
            cacc[i] = fmaf(a, bb[i * 32 + lane], cacc[i]);
    }

    // ---- c_hat = c + beta*(s - c) ----
    {
        const float beta = beta_s[w];
        const float* __restrict__ srow = s_t + (size_t)bt * 512;
        float* __restrict__ orow = out + (size_t)bt * 512;
        #pragma unroll
        for (int i = 0; i < 16; i++) {
            const int h = i * 32 + lane;
            const float sv = srow[h];
            orow[h] = fmaf(beta, sv - cacc[i], cacc[i]);
        }
    }
}

// ---------------------------------------------------------------------------
extern "C" void kernel_launch(void* const* d_in, const int* in_sizes, int n_in,
                              void* d_out, int out_size)
{
    (void)in_sizes; (void)n_in; (void)out_size;
    const float* V   = (const float*)d_in[0];
    const float* h_t = (const float*)d_in[1];
    const float* s_t = (const float*)d_in[2];
    const float* Wv  = (const float*)d_in[3];
    const float* bv  = (const float*)d_in[4];
    const float* Wg  = (const float*)d_in[5];
    const float* bg  = (const float*)d_in[6];
    const float* Ws  = (const float*)d_in[7];
    const float* bs  = (const float*)d_in[8];
    const float* Wh  = (const float*)d_in[9];
    const float* bh  = (const float*)d_in[10];
    float* out = (float*)d_out;

    dim3 blk(256);
    // cv = V @ Wv + bv : M = B*K = 784
    gemm_bias_kernel<<<dim3(4, (B_ * K_ + 127) / 128), blk>>>(V, Wv, bv, 0, B_ * K_);
    // cg = h_t @ Wg + bg : M = B*T = 4096
    gemm_bias_kernel<<<dim3(4, (B_ * T_ + 127) / 128), blk>>>(h_t, Wg, bg, 1, B_ * T_);
    // cs = s_t @ Ws + bs : M = B*T = 4096
    gemm_bias_kernel<<<dim3(4, (B_ * T_ + 127) / 128), blk>>>(s_t, Ws, bs, 2, B_ * T_);

    fused_attn_kernel<<<dim3(B_ * (T_ / 8)), blk>>>(V, s_t, Wh, bh, out);
}

// round 2
// speedup vs baseline: 2.7114x; 2.7114x over previous
#include <cuda_runtime.h>
#include <cstdint>

// Problem constants
#define B_ 16
#define K_ 49
#define T_ 256
#define H_ 512
#define D_ 512

// Output packing: (c_hat_t, alpha_t, beta_t) flattened in order
#define OUT_ALPHA (B_ * T_ * H_)              // 2097152
#define OUT_BETA  (OUT_ALPHA + B_ * T_ * K_)  // 2297856

// Scratch (device globals: allocation-free)
__device__ float g_cv[B_ * K_ * D_];   // V @ Wv + bv
__device__ float g_cg[B_ * T_ * D_];   // h_t @ Wg + bg
__device__ float g_cs[B_ * T_ * D_];   // s_t @ Ws + bs   (cg added later, in-register)

// ---------------------------------------------------------------------------
// Merged TF32 mma.sync GEMM: computes all three C[M,512] = A[M,512]@W + bias.
// 128x128 CTA tile, K-step 32, 8 warps (2m x 4n), warp tile 64x32.
// fp32 operands passed raw to tf32 mma (HW truncates mantissa).
// blockIdx.y (0..70): mt<7 -> cv (M=784), mt<39 -> cg, else cs (M=4096).
// ---------------------------------------------------------------------------
__global__ __launch_bounds__(256)
void gemm3_tf32_kernel(const float* __restrict__ V, const float* __restrict__ h_t,
                       const float* __restrict__ s_t,
                       const float* __restrict__ Wv, const float* __restrict__ bv,
                       const float* __restrict__ Wg, const float* __restrict__ bg,
                       const float* __restrict__ Wss, const float* __restrict__ bss)
{
    __shared__ float As[128 * 32];     // [m][k], k index xor-swizzled by 4*(m&7)
    __shared__ float Bs[32 * 136];     // [k][n], row stride 136 (pad 8)

    const int nt = blockIdx.x;         // 0..3
    int mt = blockIdx.y;               // 0..70
    const float *A, *W, *bias;
    float* C;
    int M;
    if (mt < 7)       { A = V;   W = Wv;  bias = bv;  C = g_cv; M = B_ * K_; }
    else if (mt < 39) { A = h_t; W = Wg;  bias = bg;  C = g_cg; M = B_ * T_; mt -= 7; }
    else              { A = s_t; W = Wss; bias = bss; C = g_cs; M = B_ * T_; mt -= 39; }

    const int tid  = threadIdx.x;
    const int lane = tid & 31;
    const int wid  = tid >> 5;
    const int g    = lane >> 2;        // 0..7
    const int tg   = lane & 3;         // 0..3
    const int warp_m = (wid >> 2) * 64;  // 0 or 64
    const int warp_n = (wid & 3) * 32;   // 0,32,64,96

    const int mbase = mt * 128;
    const int nbase = nt * 128;

    float acc[4][4][4];
    #pragma unroll
    for (int i = 0; i < 4; i++)
        #pragma unroll
        for (int j = 0; j < 4; j++)
            #pragma unroll
            for (int q = 0; q < 4; q++) acc[i][j][q] = 0.f;

    // gmem load mappings (per thread, 4 float4 each for A and W)
    const int a_m0 = tid >> 3;          // + i*32 -> m within tile
    const int a_k4 = (tid & 7) * 4;     // k within tile
    const int w_k0 = tid >> 5;          // + i*8 -> k within tile
    const int w_n4 = (tid & 31) * 4;    // n within tile

    float4 pa[4], pw[4];

    // prologue: load tile kt=0
    #pragma unroll
    for (int i = 0; i < 4; i++) {
        const int row = mbase + a_m0 + i * 32;
        pa[i] = (row < M) ? *reinterpret_cast<const float4*>(&A[(size_t)row * 512 + a_k4])
                          : make_float4(0.f, 0.f, 0.f, 0.f);
        pw[i] = *reinterpret_cast<const float4*>(&W[(size_t)(w_k0 + i * 8) * 512 + nbase + w_n4]);
    }
    #pragma unroll
    for (int i = 0; i < 4; i++) {
        const int m = a_m0 + i * 32;
        *reinterpret_cast<float4*>(&As[m * 32 + (a_k4 ^ (4 * (m & 7)))]) = pa[i];
        *reinterpret_cast<float4*>(&Bs[(w_k0 + i * 8) * 136 + w_n4]) = pw[i];
    }
    __syncthreads();

    const int sw = 4 * g;   // a-fragment swizzle (rows m0+g and m0+g+8 share it)

    for (int kt = 0; kt < 512; kt += 32) {
        // prefetch next tile into registers while mma runs on smem
        if (kt + 32 < 512) {
            #pragma unroll
            for (int i = 0; i < 4; i++) {
                const int row = mbase + a_m0 + i * 32;
                pa[i] = (row < M) ? *reinterpret_cast<const float4*>(&A[(size_t)row * 512 + kt + 32 + a_k4])
                                  : make_float4(0.f, 0.f, 0.f, 0.f);
                pw[i] = *reinterpret_cast<const float4*>(&W[(size_t)(kt + 32 + w_k0 + i * 8) * 512 + nbase + w_n4]);
            }
        }

        #pragma unroll
        for (int kb = 0; kb < 32; kb += 8) {
            uint32_t af[4][4], bf[4][2];
            #pragma unroll
            for (int mi = 0; mi < 4; mi++) {
                const int m0 = warp_m + mi * 16;
                const int k0 = (kb + tg) ^ sw;
                const int k1 = (kb + tg + 4) ^ sw;
                af[mi][0] = __float_as_uint(As[(m0 + g)     * 32 + k0]);
                af[mi][1] = __float_as_uint(As[(m0 + g + 8) * 32 + k0]);
                af[mi][2] = __float_as_uint(As[(m0 + g)     * 32 + k1]);
                af[mi][3] = __float_as_uint(As[(m0 + g + 8) * 32 + k1]);
            }
            #pragma unroll
            for (int ni = 0; ni < 4; ni++) {
                const int n_ = warp_n + ni * 8 + g;
                bf[ni][0] = __float_as_uint(Bs[(kb + tg)     * 136 + n_]);
                bf[ni][1] = __float_as_uint(Bs[(kb + tg + 4) * 136 + n_]);
            }
            #pragma unroll
            for (int mi = 0; mi < 4; mi++)
                #pragma unroll
                for (int ni = 0; ni < 4; ni++) {
                    asm volatile(
                        "mma.sync.aligned.m16n8k8.row.col.f32.tf32.tf32.f32 "
                        "{%0,%1,%2,%3}, {%4,%5,%6,%7}, {%8,%9}, {%0,%1,%2,%3};"
                        : "+f"(acc[mi][ni][0]), "+f"(acc[mi][ni][1]),
                          "+f"(acc[mi][ni][2]), "+f"(acc[mi][ni][3])
                        : "r"(af[mi][0]), "r"(af[mi][1]), "r"(af[mi][2]), "r"(af[mi][3]),
                          "r"(bf[ni][0]), "r"(bf[ni][1]));
                }
        }
        __syncthreads();
        if (kt + 32 < 512) {
            #pragma unroll
            for (int i = 0; i < 4; i++) {
                const int m = a_m0 + i * 32;
                *reinterpret_cast<float4*>(&As[m * 32 + (a_k4 ^ (4 * (m & 7)))]) = pa[i];
                *reinterpret_cast<float4*>(&Bs[(w_k0 + i * 8) * 136 + w_n4]) = pw[i];
            }
            __syncthreads();
        }
    }

    // epilogue: bias + store
    #pragma unroll
    for (int mi = 0; mi < 4; mi++) {
        const int r0 = mbase + warp_m + mi * 16 + g;
        const int r1 = r0 + 8;
        #pragma unroll
        for (int ni = 0; ni < 4; ni++) {
            const int c = nbase + warp_n + ni * 8 + tg * 2;
            const float2 bv2 = *reinterpret_cast<const float2*>(&bias[c]);
            if (r0 < M) {
                float2 o = make_float2(acc[mi][ni][0] + bv2.x, acc[mi][ni][1] + bv2.y);
                *reinterpret_cast<float2*>(&C[(size_t)r0 * 512 + c]) = o;
            }
            if (r1 < M) {
                float2 o = make_float2(acc[mi][ni][2] + bv2.x, acc[mi][ni][3] + bv2.y);
                *reinterpret_cast<float2*>(&C[(size_t)r1 * 512 + c]) = o;
            }
        }
    }
}

// tanh(x) = 1 - 2/(exp(2x)+1), computed from m = 2x*log2(e).
// ex2.approx + rcp.approx: ~1e-7 abs error, 2 MUFU ops.
__device__ __forceinline__ float tanh_from_m(float m)
{
    float e, r;
    asm("ex2.approx.f32 %0, %1;" : "=f"(e) : "f"(m));
    asm("rcp.approx.f32 %0, %1;" : "=f"(r) : "f"(e + 1.0f));
    return fmaf(-2.0f, r, 1.0f);
}

#define TWO_LOG2E 2.8853900817779268f

// ---------------------------------------------------------------------------
// Fused: z_t (tanh-dot), z_ext, softmaxes, c_t = alpha@V, blend, outputs.
// Grid: B*(T/8) = 512 blocks, 256 threads (8 warps). Warp w handles t = tile*8+w.
// ---------------------------------------------------------------------------
__global__ __launch_bounds__(256)
void fused_attn_kernel(const float* __restrict__ V, const float* __restrict__ s_t,
                       const float* __restrict__ Wh, const float* __restrict__ bh,
                       float* __restrict__ out)
{
    __shared__ float whs[512];
    __shared__ float buf[2][512];
    __shared__ float z_s[8][64];
    __shared__ float alpha_s[8][52];
    __shared__ float beta_s[8];

    const int tid  = threadIdx.x;
    const int lane = tid & 31;
    const int w    = tid >> 5;
    const int b     = blockIdx.x >> 5;
    const int ttile = blockIdx.x & 31;
    const int t  = ttile * 8 + w;
    const int bt = b * T_ + t;

    // Wh into smem
    whs[tid]       = Wh[tid];
    whs[tid + 256] = Wh[tid + 256];

    // cg row for this t, pre-scaled by 2*log2(e), register-resident
    const float* __restrict__ cgrow = g_cg + (size_t)bt * 512;
    float cg2[16];
    #pragma unroll
    for (int i = 0; i < 16; i++) cg2[i] = cgrow[i * 32 + lane] * TWO_LOG2E;

    const float bhv = bh[0];

    // ---- z_t over k, with smem-shared cv rows (double-buffered) ----
    const float* __restrict__ cvb = g_cv + (size_t)b * (K_ * 512);
    float2 pre = *reinterpret_cast<const float2*>(&cvb[tid * 2]);

    for (int k = 0; k < K_; k++) {
        *reinterpret_cast<float2*>(&buf[k & 1][tid * 2]) = pre;
        __syncthreads();
        if (k < K_ - 1)
            pre = *reinterpret_cast<const float2*>(&cvb[(k + 1) * 512 + tid * 2]);

        const float* __restrict__ bb = buf[k & 1];
        float acc = 0.f;
        #pragma unroll
        for (int i = 0; i < 16; i++) {
            float m  = fmaf(bb[i * 32 + lane], TWO_LOG2E, cg2[i]);
            float th = tanh_from_m(m);
            acc = fmaf(th, whs[i * 32 + lane], acc);
        }
        #pragma unroll
        for (int o = 16; o > 0; o >>= 1)
            acc += __shfl_xor_sync(0xffffffffu, acc, o);
        if (lane == 0) z_s[w][k] = acc + bhv;
    }

    // ---- z_ext from content_s = cs_raw + cg (per-warp, no block sync) ----
    {
        const float* __restrict__ csrow = g_cs + (size_t)bt * 512;
        float acc = 0.f;
        #pragma unroll
        for (int i = 0; i < 16; i++) {
            float m  = fmaf(csrow[i * 32 + lane], TWO_LOG2E, cg2[i]);
            float th = tanh_from_m(m);
            acc = fmaf(th, whs[i * 32 + lane], acc);
        }
        #pragma unroll
        for (int o = 16; o > 0; o >>= 1)
            acc += __shfl_xor_sync(0xffffffffu, acc, o);
        if (lane == 0) z_s[w][K_] = acc + bhv;
    }
    __syncwarp();

    // ---- softmaxes: alpha over 49, beta from extended 50 ----
    {
        float z0 = (lane < K_)      ? z_s[w][lane]      : -1e30f;
        float z1 = (lane + 32 < K_) ? z_s[w][lane + 32] : -1e30f;
        float ze = z_s[w][K_];
        float m = fmaxf(fmaxf(z0, z1), ze);
        #pragma unroll
        for (int o = 16; o > 0; o >>= 1)
            m = fmaxf(m, __shfl_xor_sync(0xffffffffu, m, o));

        float e0 = (lane < K_)      ? __expf(z0 - m) : 0.f;
        float e1 = (lane + 32 < K_) ? __expf(z1 - m) : 0.f;
        float ee = __expf(ze - m);

        float s = e0 + e1;
        #pragma unroll
        for (int o = 16; o > 0; o >>= 1)
            s += __shfl_xor_sync(0xffffffffu, s, o);
        const float s49 = s;
        const float beta = ee / (s49 + ee);
        const float inv49 = 1.0f / s49;

        if (lane < K_) {
            float a0 = e0 * inv49;
            alpha_s[w][lane] = a0;
            out[OUT_ALPHA + (size_t)bt * K_ + lane] = a0;
        }
        if (lane + 32 < K_) {
            float a1 = e1 * inv49;
            alpha_s[w][lane + 32] = a1;
            out[OUT_ALPHA + (size_t)bt * K_ + lane + 32] = a1;
        }
        if (lane == 0) {
            beta_s[w] = beta;
            out[OUT_BETA + bt] = beta;
        }
    }

    // ---- c_t = alpha @ V, with smem-shared V rows ----
    float cacc[16];
    #pragma unroll
    for (int i = 0; i < 16; i++) cacc[i] = 0.f;

    const float* __restrict__ Vb = V + (size_t)b * (K_ * 512);
    pre = *reinterpret_cast<const float2*>(&Vb[tid * 2]);
    __syncthreads();   // everyone done reading buf from the z-loop

    for (int k = 0; k < K_; k++) {
        *reinterpret_cast<float2*>(&buf[k & 1][tid * 2]) = pre;
        __syncthreads();
        if (k < K_ - 1)
            pre = *reinterpret_cast<const float2*>(&Vb[(k + 1) * 512 + tid * 2]);

        const float a = alpha_s[w][k];
        const float* __restrict__ bb = buf[k & 1];
        #pragma unroll
        for (int i = 0; i < 16; i++)
            cacc[i] = fmaf(a, bb[i * 32 + lane], cacc[i]);
    }

    // ---- c_hat = c + beta*(s - c) ----
    {
        const float beta = beta_s[w];
        const float* __restrict__ srow = s_t + (size_t)bt * 512;
        float* __restrict__ orow = out + (size_t)bt * 512;
        #pragma unroll
        for (int i = 0; i < 16; i++) {
            const int h = i * 32 + lane;
            const float sv = srow[h];
            orow[h] = fmaf(beta, sv - cacc[i], cacc[i]);
        }
    }
}

// ---------------------------------------------------------------------------
extern "C" void kernel_launch(void* const* d_in, const int* in_sizes, int n_in,
                              void* d_out, int out_size)
{
    (void)in_sizes; (void)n_in; (void)out_size;
    const float* V   = (const float*)d_in[0];
    const float* h_t = (const float*)d_in[1];
    const float* s_t = (const float*)d_in[2];
    const float* Wv  = (const float*)d_in[3];
    const float* bv  = (const float*)d_in[4];
    const float* Wg  = (const float*)d_in[5];
    const float* bg  = (const float*)d_in[6];
    const float* Ws  = (const float*)d_in[7];
    const float* bs  = (const float*)d_in[8];
    const float* Wh  = (const float*)d_in[9];
    const float* bh  = (const float*)d_in[10];
    float* out = (float*)d_out;

    // All three GEMMs in one launch: grid (4 n-tiles, 7+32+32 m-tiles)
    gemm3_tf32_kernel<<<dim3(4, 71), 256>>>(V, h_t, s_t, Wv, bv, Wg, bg, Ws, bs);

    fused_attn_kernel<<<dim3(B_ * (T_ / 8)), 256>>>(V, s_t, Wh, bh, out);
}

// round 3
// speedup vs baseline: 3.2621x; 1.2031x over previous
#include <cuda_runtime.h>
#include <cstdint>

// Problem constants
#define B_ 16
#define K_ 49
#define T_ 256
#define H_ 512
#define D_ 512

// Output packing: (c_hat_t, alpha_t, beta_t) flattened in order
#define OUT_ALPHA (B_ * T_ * H_)              // 2097152
#define OUT_BETA  (OUT_ALPHA + B_ * T_ * K_)  // 2297856

// Scratch (device globals: allocation-free)
__device__ float g_cv[B_ * K_ * D_];   // V @ Wv + bv
__device__ float g_cg[B_ * T_ * D_];   // h_t @ Wg + bg
__device__ float g_cs[B_ * T_ * D_];   // s_t @ Ws + bs   (cg added later, in-register)

// ---------------------------------------------------------------------------
// Merged TF32 mma.sync GEMM: computes all three C[M,512] = A[M,512]@W + bias.
// 128x128 CTA tile, K-step 32, 8 warps (2m x 4n), warp tile 64x32.
// ---------------------------------------------------------------------------
__global__ __launch_bounds__(256)
void gemm3_tf32_kernel(const float* __restrict__ V, const float* __restrict__ h_t,
                       const float* __restrict__ s_t,
                       const float* __restrict__ Wv, const float* __restrict__ bv,
                       const float* __restrict__ Wg, const float* __restrict__ bg,
                       const float* __restrict__ Wss, const float* __restrict__ bss)
{
    __shared__ float As[128 * 32];     // [m][k], k index xor-swizzled by 4*(m&7)
    __shared__ float Bs[32 * 136];     // [k][n], row stride 136 (pad 8)

    const int nt = blockIdx.x;         // 0..3
    int mt = blockIdx.y;               // 0..70
    const float *A, *W, *bias;
    float* C;
    int M;
    if (mt < 7)       { A = V;   W = Wv;  bias = bv;  C = g_cv; M = B_ * K_; }
    else if (mt < 39) { A = h_t; W = Wg;  bias = bg;  C = g_cg; M = B_ * T_; mt -= 7; }
    else              { A = s_t; W = Wss; bias = bss; C = g_cs; M = B_ * T_; mt -= 39; }

    const int tid  = threadIdx.x;
    const int lane = tid & 31;
    const int wid  = tid >> 5;
    const int g    = lane >> 2;        // 0..7
    const int tg   = lane & 3;         // 0..3
    const int warp_m = (wid >> 2) * 64;  // 0 or 64
    const int warp_n = (wid & 3) * 32;   // 0,32,64,96

    const int mbase = mt * 128;
    const int nbase = nt * 128;

    float acc[4][4][4];
    #pragma unroll
    for (int i = 0; i < 4; i++)
        #pragma unroll
        for (int j = 0; j < 4; j++)
            #pragma unroll
            for (int q = 0; q < 4; q++) acc[i][j][q] = 0.f;

    const int a_m0 = tid >> 3;          // + i*32 -> m within tile
    const int a_k4 = (tid & 7) * 4;     // k within tile
    const int w_k0 = tid >> 5;          // + i*8 -> k within tile
    const int w_n4 = (tid & 31) * 4;    // n within tile

    float4 pa[4], pw[4];

    #pragma unroll
    for (int i = 0; i < 4; i++) {
        const int row = mbase + a_m0 + i * 32;
        pa[i] = (row < M) ? *reinterpret_cast<const float4*>(&A[(size_t)row * 512 + a_k4])
                          : make_float4(0.f, 0.f, 0.f, 0.f);
        pw[i] = *reinterpret_cast<const float4*>(&W[(size_t)(w_k0 + i * 8) * 512 + nbase + w_n4]);
    }
    #pragma unroll
    for (int i = 0; i < 4; i++) {
        const int m = a_m0 + i * 32;
        *reinterpret_cast<float4*>(&As[m * 32 + (a_k4 ^ (4 * (m & 7)))]) = pa[i];
        *reinterpret_cast<float4*>(&Bs[(w_k0 + i * 8) * 136 + w_n4]) = pw[i];
    }
    __syncthreads();

    const int sw = 4 * g;

    for (int kt = 0; kt < 512; kt += 32) {
        if (kt + 32 < 512) {
            #pragma unroll
            for (int i = 0; i < 4; i++) {
                const int row = mbase + a_m0 + i * 32;
                pa[i] = (row < M) ? *reinterpret_cast<const float4*>(&A[(size_t)row * 512 + kt + 32 + a_k4])
                                  : make_float4(0.f, 0.f, 0.f, 0.f);
                pw[i] = *reinterpret_cast<const float4*>(&W[(size_t)(kt + 32 + w_k0 + i * 8) * 512 + nbase + w_n4]);
            }
        }

        #pragma unroll
        for (int kb = 0; kb < 32; kb += 8) {
            uint32_t af[4][4], bf[4][2];
            #pragma unroll
            for (int mi = 0; mi < 4; mi++) {
                const int m0 = warp_m + mi * 16;
                const int k0 = (kb + tg) ^ sw;
                const int k1 = (kb + tg + 4) ^ sw;
                af[mi][0] = __float_as_uint(As[(m0 + g)     * 32 + k0]);
                af[mi][1] = __float_as_uint(As[(m0 + g + 8) * 32 + k0]);
                af[mi][2] = __float_as_uint(As[(m0 + g)     * 32 + k1]);
                af[mi][3] = __float_as_uint(As[(m0 + g + 8) * 32 + k1]);
            }
            #pragma unroll
            for (int ni = 0; ni < 4; ni++) {
                const int n_ = warp_n + ni * 8 + g;
                bf[ni][0] = __float_as_uint(Bs[(kb + tg)     * 136 + n_]);
                bf[ni][1] = __float_as_uint(Bs[(kb + tg + 4) * 136 + n_]);
            }
            #pragma unroll
            for (int mi = 0; mi < 4; mi++)
                #pragma unroll
                for (int ni = 0; ni < 4; ni++) {
                    asm volatile(
                        "mma.sync.aligned.m16n8k8.row.col.f32.tf32.tf32.f32 "
                        "{%0,%1,%2,%3}, {%4,%5,%6,%7}, {%8,%9}, {%0,%1,%2,%3};"
                        : "+f"(acc[mi][ni][0]), "+f"(acc[mi][ni][1]),
                          "+f"(acc[mi][ni][2]), "+f"(acc[mi][ni][3])
                        : "r"(af[mi][0]), "r"(af[mi][1]), "r"(af[mi][2]), "r"(af[mi][3]),
                          "r"(bf[ni][0]), "r"(bf[ni][1]));
                }
        }
        __syncthreads();
        if (kt + 32 < 512) {
            #pragma unroll
            for (int i = 0; i < 4; i++) {
                const int m = a_m0 + i * 32;
                *reinterpret_cast<float4*>(&As[m * 32 + (a_k4 ^ (4 * (m & 7)))]) = pa[i];
                *reinterpret_cast<float4*>(&Bs[(w_k0 + i * 8) * 136 + w_n4]) = pw[i];
            }
            __syncthreads();
        }
    }

    #pragma unroll
    for (int mi = 0; mi < 4; mi++) {
        const int r0 = mbase + warp_m + mi * 16 + g;
        const int r1 = r0 + 8;
        #pragma unroll
        for (int ni = 0; ni < 4; ni++) {
            const int c = nbase + warp_n + ni * 8 + tg * 2;
            const float2 bv2 = *reinterpret_cast<const float2*>(&bias[c]);
            if (r0 < M) {
                float2 o = make_float2(acc[mi][ni][0] + bv2.x, acc[mi][ni][1] + bv2.y);
                *reinterpret_cast<float2*>(&C[(size_t)r0 * 512 + c]) = o;
            }
            if (r1 < M) {
                float2 o = make_float2(acc[mi][ni][2] + bv2.x, acc[mi][ni][3] + bv2.y);
                *reinterpret_cast<float2*>(&C[(size_t)r1 * 512 + c]) = o;
            }
        }
    }
}

// Single-MUFU tanh (MUFU.TANH on sm_75+). Max abs err ~5e-4.
__device__ __forceinline__ float tanha(float x)
{
    float r;
    asm("tanh.approx.f32 %0, %1;" : "=f"(r) : "f"(x));
    return r;
}

// ---------------------------------------------------------------------------
// Fused: z_t (tanh-dot), z_ext, softmaxes, c_t = alpha@V, blend, outputs.
// Grid: B*(T/8) = 512 blocks, 256 threads (8 warps). Warp w handles t = tile*8+w.
// Lane owns d in [16*lane, 16*lane+16): cg & Wh register-resident, float4 smem/gmem IO.
// Smem rows XOR-swizzled on 16B chunks (c ^= (c>>3)&7) -> conflict-free LDS.128/STS.64.
// ---------------------------------------------------------------------------
__global__ __launch_bounds__(256)
void fused_attn_kernel(const float* __restrict__ V, const float* __restrict__ s_t,
                       const float* __restrict__ Wh, const float* __restrict__ bh,
                       float* __restrict__ out)
{
    __shared__ float buf[2][512];
    __shared__ float z_s[8][64];
    __shared__ float alpha_s[8][52];
    __shared__ float beta_s[8];

    const int tid  = threadIdx.x;
    const int lane = tid & 31;
    const int w    = tid >> 5;
    const int b     = blockIdx.x >> 5;
    const int ttile = blockIdx.x & 31;
    const int t  = ttile * 8 + w;
    const int bt = b * T_ + t;

    // swizzle maps: writer (float2 at float-index 2*tid), reader (float4 chunks)
    const int wchunk = tid >> 1;
    const int wsw = ((wchunk ^ ((wchunk >> 3) & 7)) << 2) + ((tid & 1) << 1);
    int rsw[4];
    #pragma unroll
    for (int j = 0; j < 4; j++) {
        const int c = lane * 4 + j;
        rsw[j] = (c ^ ((c >> 3) & 7)) << 2;
    }

    // cg row and Wh: register-resident, 16 contiguous d per lane
    float cgr[16], whr[16];
    {
        const float* __restrict__ cgrow = g_cg + (size_t)bt * 512 + lane * 16;
        const float* __restrict__ whrow = Wh + lane * 16;
        #pragma unroll
        for (int j = 0; j < 4; j++) {
            float4 a = *reinterpret_cast<const float4*>(&cgrow[j * 4]);
            float4 c = *reinterpret_cast<const float4*>(&whrow[j * 4]);
            cgr[j * 4 + 0] = a.x; cgr[j * 4 + 1] = a.y; cgr[j * 4 + 2] = a.z; cgr[j * 4 + 3] = a.w;
            whr[j * 4 + 0] = c.x; whr[j * 4 + 1] = c.y; whr[j * 4 + 2] = c.z; whr[j * 4 + 3] = c.w;
        }
    }
    const float bhv = bh[0];

    // ---- z_t over k, smem-shared cv rows (double-buffered, swizzled) ----
    const float* __restrict__ cvb = g_cv + (size_t)b * (K_ * 512);
    float2 pre = *reinterpret_cast<const float2*>(&cvb[tid * 2]);

    for (int k = 0; k < K_; k++) {
        *reinterpret_cast<float2*>(&buf[k & 1][wsw]) = pre;
        __syncthreads();
        if (k < K_ - 1)
            pre = *reinterpret_cast<const float2*>(&cvb[(k + 1) * 512 + tid * 2]);

        const float* __restrict__ bb = buf[k & 1];
        float acc = 0.f;
        #pragma unroll
        for (int j = 0; j < 4; j++) {
            float4 v = *reinterpret_cast<const float4*>(&bb[rsw[j]]);
            acc = fmaf(tanha(v.x + cgr[j * 4 + 0]), whr[j * 4 + 0], acc);
            acc = fmaf(tanha(v.y + cgr[j * 4 + 1]), whr[j * 4 + 1], acc);
            acc = fmaf(tanha(v.z + cgr[j * 4 + 2]), whr[j * 4 + 2], acc);
            acc = fmaf(tanha(v.w + cgr[j * 4 + 3]), whr[j * 4 + 3], acc);
        }
        #pragma unroll
        for (int o = 16; o > 0; o >>= 1)
            acc += __shfl_xor_sync(0xffffffffu, acc, o);
        if (lane == 0) z_s[w][k] = acc + bhv;
    }

    // ---- z_ext from content_s = cs_raw + cg (per-warp) ----
    {
        const float* __restrict__ csrow = g_cs + (size_t)bt * 512 + lane * 16;
        float acc = 0.f;
        #pragma unroll
        for (int j = 0; j < 4; j++) {
            float4 v = *reinterpret_cast<const float4*>(&csrow[j * 4]);
            acc = fmaf(tanha(v.x + cgr[j * 4 + 0]), whr[j * 4 + 0], acc);
            acc = fmaf(tanha(v.y + cgr[j * 4 + 1]), whr[j * 4 + 1], acc);
            acc = fmaf(tanha(v.z + cgr[j * 4 + 2]), whr[j * 4 + 2], acc);
            acc = fmaf(tanha(v.w + cgr[j * 4 + 3]), whr[j * 4 + 3], acc);
        }
        #pragma unroll
        for (int o = 16; o > 0; o >>= 1)
            acc += __shfl_xor_sync(0xffffffffu, acc, o);
        if (lane == 0) z_s[w][K_] = acc + bhv;
    }
    __syncwarp();

    // ---- softmaxes: alpha over 49, beta from extended 50 ----
    {
        float z0 = (lane < K_)      ? z_s[w][lane]      : -1e30f;
        float z1 = (lane + 32 < K_) ? z_s[w][lane + 32] : -1e30f;
        float ze = z_s[w][K_];
        float m = fmaxf(fmaxf(z0, z1), ze);
        #pragma unroll
        for (int o = 16; o > 0; o >>= 1)
            m = fmaxf(m, __shfl_xor_sync(0xffffffffu, m, o));

        float e0 = (lane < K_)      ? __expf(z0 - m) : 0.f;
        float e1 = (lane + 32 < K_) ? __expf(z1 - m) : 0.f;
        float ee = __expf(ze - m);

        float s = e0 + e1;
        #pragma unroll
        for (int o = 16; o > 0; o >>= 1)
            s += __shfl_xor_sync(0xffffffffu, s, o);
        const float s49 = s;
        const float beta = ee / (s49 + ee);
        const float inv49 = 1.0f / s49;

        if (lane < K_) {
            float a0 = e0 * inv49;
            alpha_s[w][lane] = a0;
            out[OUT_ALPHA + (size_t)bt * K_ + lane] = a0;
        }
        if (lane + 32 < K_) {
            float a1 = e1 * inv49;
            alpha_s[w][lane + 32] = a1;
            out[OUT_ALPHA + (size_t)bt * K_ + lane + 32] = a1;
        }
        if (lane == 0) {
            beta_s[w] = beta;
            out[OUT_BETA + bt] = beta;
        }
    }

    // ---- c_t = alpha @ V, smem-shared V rows ----
    float cacc[16];
    #pragma unroll
    for (int i = 0; i < 16; i++) cacc[i] = 0.f;

    const float* __restrict__ Vb = V + (size_t)b * (K_ * 512);
    pre = *reinterpret_cast<const float2*>(&Vb[tid * 2]);
    __syncthreads();   // all warps done with buf from z-loop + alpha_s visible

    for (int k = 0; k < K_; k++) {
        *reinterpret_cast<float2*>(&buf[k & 1][wsw]) = pre;
        __syncthreads();
        if (k < K_ - 1)
            pre = *reinterpret_cast<const float2*>(&Vb[(k + 1) * 512 + tid * 2]);

        const float a = alpha_s[w][k];
        const float* __restrict__ bb = buf[k & 1];
        #pragma unroll
        for (int j = 0; j < 4; j++) {
            float4 v = *reinterpret_cast<const float4*>(&bb[rsw[j]]);
            cacc[j * 4 + 0] = fmaf(a, v.x, cacc[j * 4 + 0]);
            cacc[j * 4 + 1] = fmaf(a, v.y, cacc[j * 4 + 1]);
            cacc[j * 4 + 2] = fmaf(a, v.z, cacc[j * 4 + 2]);
            cacc[j * 4 + 3] = fmaf(a, v.w, cacc[j * 4 + 3]);
        }
    }

    // ---- c_hat = c + beta*(s - c) ----
    {
        const float beta = beta_s[w];
        const float* __restrict__ srow = s_t + (size_t)bt * 512 + lane * 16;
        float* __restrict__ orow = out + (size_t)bt * 512 + lane * 16;
        #pragma unroll
        for (int j = 0; j < 4; j++) {
            float4 sv = *reinterpret_cast<const float4*>(&srow[j * 4]);
            float4 o;
            o.x = fmaf(beta, sv.x - cacc[j * 4 + 0], cacc[j * 4 + 0]);
            o.y = fmaf(beta, sv.y - cacc[j * 4 + 1], cacc[j * 4 + 1]);
            o.z = fmaf(beta, sv.z - cacc[j * 4 + 2], cacc[j * 4 + 2]);
            o.w = fmaf(beta, sv.w - cacc[j * 4 + 3], cacc[j * 4 + 3]);
            *reinterpret_cast<float4*>(&orow[j * 4]) = o;
        }
    }
}

// ---------------------------------------------------------------------------
extern "C" void kernel_launch(void* const* d_in, const int* in_sizes, int n_in,
                              void* d_out, int out_size)
{
    (void)in_sizes; (void)n_in; (void)out_size;
    const float* V   = (const float*)d_in[0];
    const float* h_t = (const float*)d_in[1];
    const float* s_t = (const float*)d_in[2];
    const float* Wv  = (const float*)d_in[3];
    const float* bv  = (const float*)d_in[4];
    const float* Wg  = (const float*)d_in[5];
    const float* bg  = (const float*)d_in[6];
    const float* Ws  = (const float*)d_in[7];
    const float* bs  = (const float*)d_in[8];
    const float* Wh  = (const float*)d_in[9];
    const float* bh  = (const float*)d_in[10];
    float* out = (float*)d_out;

    gemm3_tf32_kernel<<<dim3(4, 71), 256>>>(V, h_t, s_t, Wv, bv, Wg, bg, Ws, bs);
    fused_attn_kernel<<<dim3(B_ * (T_ / 8)), 256>>>(V, s_t, Wh, bh, out);
}